// round 3
// baseline (speedup 1.0000x reference)
#include <cuda_runtime.h>
#include <float.h>

#define BATCH 64
#define TOK   2048
#define DIM   768
#define POOL  1024
#define TOPK  8
#define SPLITS 32
#define TOKS  (TOK / SPLITS)   // 64 tokens per split
#define D4    (DIM / 4)        // 192 float4 per row
#define NK    24               // K-splits for GEMMs
#define KC    32               // K-chunk per split (768/24)

// ---- scratch (static device arrays; no cudaMalloc anywhere) ----
__device__ float g_part[SPLITS * BATCH * DIM];     // token-max partials
__device__ float g_xmean[BATCH * DIM];
__device__ float g_invp[POOL];
__device__ float g_xnorm[BATCH * DIM];
__device__ float g_ppart[NK * BATCH * DIM];        // proj split-K partials
__device__ float g_spart[NK * BATCH * POOL];       // sim split-K partials
__device__ float g_sim[BATCH * POOL];
__device__ int   g_rowidx[BATCH * TOPK];
__device__ int   g_major[TOPK];

__device__ __forceinline__ float4 fmax4(float4 a, float4 b) {
    return make_float4(fmaxf(a.x, b.x), fmaxf(a.y, b.y),
                       fmaxf(a.z, b.z), fmaxf(a.w, b.w));
}

// ================= stage 1: token-max (HBM-bound 403 MB stream) =============
// grid (SPLITS, BATCH), block 192
__global__ void k_maxpart(const float* __restrict__ x) {
    int s = blockIdx.x, b = blockIdx.y, tid = threadIdx.x;
    const float4* xp = (const float4*)x + ((size_t)b * TOK + (size_t)s * TOKS) * D4;
    float4 m0 = xp[0 * D4 + tid];
    float4 m1 = xp[1 * D4 + tid];
    float4 m2 = xp[2 * D4 + tid];
    float4 m3 = xp[3 * D4 + tid];
#pragma unroll 4
    for (int t = 4; t < TOKS; t += 4) {
        m0 = fmax4(m0, xp[(t + 0) * D4 + tid]);
        m1 = fmax4(m1, xp[(t + 1) * D4 + tid]);
        m2 = fmax4(m2, xp[(t + 2) * D4 + tid]);
        m3 = fmax4(m3, xp[(t + 3) * D4 + tid]);
    }
    ((float4*)g_part)[(s * BATCH + b) * D4 + tid] = fmax4(fmax4(m0, m1), fmax4(m2, m3));
}

// ================= stage 2 (fused): final max + prompt inv-norms =============
// grid BATCH + ceil(POOL/6), block 192
__global__ void k_mf_pn(const float* __restrict__ prompt) {
    int tid = threadIdx.x;
    if (blockIdx.x < BATCH) {
        int b = blockIdx.x;
        const float4* p4 = (const float4*)g_part;
        float4 m0 = p4[(0 * BATCH + b) * D4 + tid];
        float4 m1 = p4[(1 * BATCH + b) * D4 + tid];
        float4 m2 = p4[(2 * BATCH + b) * D4 + tid];
        float4 m3 = p4[(3 * BATCH + b) * D4 + tid];
#pragma unroll
        for (int s = 4; s < SPLITS; s += 4) {
            m0 = fmax4(m0, p4[((s + 0) * BATCH + b) * D4 + tid]);
            m1 = fmax4(m1, p4[((s + 1) * BATCH + b) * D4 + tid]);
            m2 = fmax4(m2, p4[((s + 2) * BATCH + b) * D4 + tid]);
            m3 = fmax4(m3, p4[((s + 3) * BATCH + b) * D4 + tid]);
        }
        ((float4*)g_xmean)[b * D4 + tid] = fmax4(fmax4(m0, m1), fmax4(m2, m3));
    } else {
        int w = tid >> 5, lane = tid & 31;
        int p = (blockIdx.x - BATCH) * 6 + w;
        if (p < POOL) {
            const float* row = prompt + (size_t)p * DIM;
            float s = 0.f;
#pragma unroll
            for (int j = lane; j < DIM; j += 32) { float v = row[j]; s += v * v; }
#pragma unroll
            for (int o = 16; o > 0; o >>= 1) s += __shfl_xor_sync(0xffffffffu, s, o);
            if (lane == 0) g_invp[p] = rsqrtf(fmaxf(s, 1e-12f));
        }
    }
}

// ================= split-K GEMM: C_part[split] = A(64xKC) @ B_tile^T =========
// block 256, 64 rows x 64 cols per CTA per K-chunk of 32.
__device__ __forceinline__ void gemm_part_body(
    const float* __restrict__ A, const float* __restrict__ B,
    float* __restrict__ part, int cstride)
{
    __shared__ float xs[64][36];
    __shared__ float ws[64][36];
    int tid = threadIdx.x;
    int kc0 = blockIdx.y * KC;
    int c0  = blockIdx.x * 64;
#pragma unroll
    for (int it = 0; it < 2; it++) {
        int idx = tid + it * 256;          // 0..511
        int r = idx >> 3, c4 = idx & 7;    // 8 float4 per 32-float row
        *(float4*)&xs[r][c4 * 4] = *(const float4*)(A + (size_t)r * DIM + kc0 + c4 * 4);
        *(float4*)&ws[r][c4 * 4] = *(const float4*)(B + (size_t)(c0 + r) * DIM + kc0 + c4 * 4);
    }
    __syncthreads();
    int tx = tid & 15, ty = tid >> 4;      // 16 x 16 threads, 4x4 micro-tile
    float acc[4][4];
#pragma unroll
    for (int i = 0; i < 4; i++)
#pragma unroll
        for (int j = 0; j < 4; j++) acc[i][j] = 0.f;
#pragma unroll
    for (int k4 = 0; k4 < KC / 4; k4++) {
        float4 a[4], b[4];
#pragma unroll
        for (int i = 0; i < 4; i++) a[i] = *(float4*)&xs[ty * 4 + i][k4 * 4];
#pragma unroll
        for (int j = 0; j < 4; j++) b[j] = *(float4*)&ws[tx * 4 + j][k4 * 4];
#pragma unroll
        for (int i = 0; i < 4; i++)
#pragma unroll
            for (int j = 0; j < 4; j++) {
                acc[i][j] += a[i].x * b[j].x;
                acc[i][j] += a[i].y * b[j].y;
                acc[i][j] += a[i].z * b[j].z;
                acc[i][j] += a[i].w * b[j].w;
            }
    }
    float* dst = part + (size_t)blockIdx.y * BATCH * cstride;
#pragma unroll
    for (int i = 0; i < 4; i++) {
        float4 v = make_float4(acc[i][0], acc[i][1], acc[i][2], acc[i][3]);
        *(float4*)(dst + (size_t)(ty * 4 + i) * cstride + c0 + tx * 4) = v;
    }
}

// grid (DIM/64, NK)
__global__ void __launch_bounds__(256) k_proj_part(const float* __restrict__ W) {
    gemm_part_body(g_xmean, W, g_ppart, DIM);
}
// grid (POOL/64, NK)
__global__ void __launch_bounds__(256) k_sim_part(const float* __restrict__ prompt) {
    gemm_part_body(g_xnorm, prompt, g_spart, POOL);
}

// ================= reduce proj partials + row L2-normalize ===================
// grid BATCH, block 256
__global__ void k_xnorm_red() {
    __shared__ float red[256];
    __shared__ float s_inv;
    int b = blockIdx.x, tid = threadIdx.x;
    float v[3];
    float ss = 0.f;
#pragma unroll
    for (int j = 0; j < 3; j++) {
        int col = tid + 256 * j;
        float s = 0.f;
#pragma unroll
        for (int sp = 0; sp < NK; sp++)
            s += g_ppart[(size_t)sp * BATCH * DIM + (size_t)b * DIM + col];
        v[j] = s;
        ss += s * s;
    }
    red[tid] = ss; __syncthreads();
    for (int st = 128; st > 0; st >>= 1) {
        if (tid < st) red[tid] += red[tid + st];
        __syncthreads();
    }
    if (tid == 0) s_inv = rsqrtf(fmaxf(red[0], 1e-12f));
    __syncthreads();
    float inv = s_inv;
#pragma unroll
    for (int j = 0; j < 3; j++)
        g_xnorm[b * DIM + tid + 256 * j] = v[j] * inv;
}

// ====== fused: reduce sim partials + scale + per-row top-8 ====================
// grid BATCH, block 256
__global__ void k_simtop() {
    __shared__ float sv[POOL];
    __shared__ float rv[256];
    __shared__ int   ri[256];
    int b = blockIdx.x, tid = threadIdx.x;
#pragma unroll
    for (int j = 0; j < 4; j++) {
        int p = tid + 256 * j;
        float s = 0.f;
#pragma unroll
        for (int sp = 0; sp < NK; sp++)
            s += g_spart[(size_t)sp * BATCH * POOL + (size_t)b * POOL + p];
        s *= g_invp[p];
        sv[p] = s;
        g_sim[b * POOL + p] = s;   // vote kernel reads this
    }
    __syncthreads();
    for (int k = 0; k < TOPK; k++) {
        float bv = -FLT_MAX; int bi = 0;
#pragma unroll
        for (int j = 0; j < 4; j++) {
            int i = tid + 256 * j;
            float v = sv[i];
            if (v > bv) { bv = v; bi = i; }   // ascending i: lowest index on tie
        }
        rv[tid] = bv; ri[tid] = bi; __syncthreads();
        for (int st = 128; st > 0; st >>= 1) {
            if (tid < st) {
                float v2 = rv[tid + st]; int i2 = ri[tid + st];
                if (v2 > rv[tid] || (v2 == rv[tid] && i2 < ri[tid])) { rv[tid] = v2; ri[tid] = i2; }
            }
            __syncthreads();
        }
        if (tid == 0) { g_rowidx[b * TOPK + k] = ri[0]; sv[ri[0]] = -FLT_MAX; }
        __syncthreads();
    }
}

// ================= vote (bincount + top-8 over counts) + reduce_sim ==========
// single block, 256 threads
__global__ void k_vote(float* __restrict__ out) {
    __shared__ int   cnt[POOL];
    __shared__ int   rvi[256];
    __shared__ int   ri[256];
    __shared__ float rf[256];
    __shared__ int   major_s[TOPK];
    int tid = threadIdx.x;
    for (int j = tid; j < POOL; j += 256) cnt[j] = 0;
    __syncthreads();
    for (int j = tid; j < BATCH * TOPK; j += 256) atomicAdd(&cnt[g_rowidx[j]], 1);
    __syncthreads();
    for (int k = 0; k < TOPK; k++) {
        int bv = -1, bi = 0;
        for (int j = tid; j < POOL; j += 256) {
            int c = cnt[j];
            if (c > bv) { bv = c; bi = j; }   // ascending j: lowest index on tie
        }
        rvi[tid] = bv; ri[tid] = bi; __syncthreads();
        for (int st = 128; st > 0; st >>= 1) {
            if (tid < st) {
                int v2 = rvi[tid + st], i2 = ri[tid + st];
                if (v2 > rvi[tid] || (v2 == rvi[tid] && i2 < ri[tid])) { rvi[tid] = v2; ri[tid] = i2; }
            }
            __syncthreads();
        }
        if (tid == 0) { major_s[k] = ri[0]; g_major[k] = ri[0]; cnt[ri[0]] = -1; }
        __syncthreads();
    }
    float s = 0.f;
    for (int j = tid; j < BATCH * TOPK; j += 256) {
        int b = j >> 3, k = j & 7;
        s += g_sim[b * POOL + major_s[k]];
    }
    rf[tid] = s; __syncthreads();
    for (int st = 128; st > 0; st >>= 1) {
        if (tid < st) rf[tid] += rf[tid + st];
        __syncthreads();
    }
    if (tid == 0) out[0] = rf[0] / (float)BATCH;
}

// ================= gather batched_prompt =====================================
// grid BATCH*TOPK, block 192
__global__ void k_gather(const float* __restrict__ prompt, float* __restrict__ out) {
    int row = blockIdx.x;            // b*8 + k
    int k = row & 7;
    int pid = g_major[k];
    const float* src = prompt + (size_t)pid * DIM;
    float* dst = out + 1 + (size_t)row * DIM;
    dst[threadIdx.x]       = src[threadIdx.x];
    dst[threadIdx.x + 192] = src[threadIdx.x + 192];
    dst[threadIdx.x + 384] = src[threadIdx.x + 384];
    dst[threadIdx.x + 576] = src[threadIdx.x + 576];
}

extern "C" void kernel_launch(void* const* d_in, const int* in_sizes, int n_in,
                              void* d_out, int out_size) {
    const float* x      = (const float*)d_in[0];   // [64, 2048, 768]
    const float* prompt = (const float*)d_in[1];   // [1024, 768]
    const float* W      = (const float*)d_in[2];   // [768, 768]
    float* out = (float*)d_out;                    // [1 + 64*8*768]

    k_maxpart  <<<dim3(SPLITS, BATCH), D4>>>(x);
    k_mf_pn    <<<BATCH + (POOL + 5) / 6, 192>>>(prompt);
    k_proj_part<<<dim3(DIM / 64, NK), 256>>>(W);
    k_xnorm_red<<<BATCH, 256>>>();
    k_sim_part <<<dim3(POOL / 64, NK), 256>>>(prompt);
    k_simtop   <<<BATCH, 256>>>();
    k_vote     <<<1, 256>>>(out);
    k_gather   <<<BATCH * TOPK, 192>>>(prompt, out);
}

// round 5
// speedup vs baseline: 1.0463x; 1.0463x over previous
#include <cuda_runtime.h>
#include <float.h>

#define BATCH 64
#define TOK   2048
#define DIM   768
#define POOL  1024
#define TOPK  8
#define SPLITS 32
#define TOKS  64               // tokens per tile
#define D4    192              // float4 per row
#define NK    12               // split-K
#define KC    64               // K chunk
#define G     296              // persistent grid: 2 CTAs/SM on 148 SMs

// ---- scratch (static device arrays; no cudaMalloc anywhere) ----
__device__ float g_part[SPLITS * BATCH * DIM];
__device__ float g_xmean[BATCH * DIM];
__device__ float g_invp[POOL];
__device__ float g_xnorm[BATCH * DIM];
__device__ float g_ppart[NK * BATCH * DIM];
__device__ float g_spart[NK * BATCH * POOL];
__device__ float g_sim[BATCH * POOL];
__device__ int   g_rowidx[BATCH * TOPK];
__device__ int   g_major[TOPK];
__device__ unsigned g_count = 0;   // barrier state: self-resetting across replays
__device__ unsigned g_gen   = 0;

__device__ __forceinline__ float4 fmax4(float4 a, float4 b) {
    return make_float4(fmaxf(a.x, b.x), fmaxf(a.y, b.y),
                       fmaxf(a.z, b.z), fmaxf(a.w, b.w));
}

// software grid barrier (all G CTAs resident by construction)
__device__ __forceinline__ void grid_sync() {
    __syncthreads();
    if (threadIdx.x == 0) {
        __threadfence();
        volatile unsigned* genp = &g_gen;
        unsigned gen = *genp;
        if (atomicAdd(&g_count, 1u) == G - 1) {
            *(volatile unsigned*)&g_count = 0;
            __threadfence();
            *genp = gen + 1;
        } else {
            while (*genp == gen) __nanosleep(32);
        }
        __threadfence();
    }
    __syncthreads();
}

// 64x64 output tile GEMM chunk over KC=64 K-slice (A,B row-major, dot along DIM)
__device__ __forceinline__ void gemm64(const float* __restrict__ A,
                                       const float* __restrict__ B,
                                       float* __restrict__ dst, int cstride,
                                       int kc0, int c0, float* pool) {
    float (*xs)[68] = (float(*)[68])pool;
    float (*ws)[68] = (float(*)[68])(pool + 64 * 68);
    int tid = threadIdx.x;
#pragma unroll
    for (int it = 0; it < 4; it++) {
        int idx = tid + it * 256;          // 0..1023
        int r = idx >> 4, c4 = idx & 15;
        *(float4*)&xs[r][c4 * 4] = *(const float4*)(A + (size_t)r * DIM + kc0 + c4 * 4);
        *(float4*)&ws[r][c4 * 4] = *(const float4*)(B + (size_t)(c0 + r) * DIM + kc0 + c4 * 4);
    }
    __syncthreads();
    int tx = tid & 15, ty = tid >> 4;      // 16x16 threads, 4x4 micro-tile
    float acc[4][4];
#pragma unroll
    for (int i = 0; i < 4; i++)
#pragma unroll
        for (int j = 0; j < 4; j++) acc[i][j] = 0.f;
#pragma unroll
    for (int k4 = 0; k4 < KC / 4; k4++) {
        float4 a[4], b[4];
#pragma unroll
        for (int i = 0; i < 4; i++) a[i] = *(float4*)&xs[ty * 4 + i][k4 * 4];
#pragma unroll
        for (int j = 0; j < 4; j++) b[j] = *(float4*)&ws[tx * 4 + j][k4 * 4];
#pragma unroll
        for (int i = 0; i < 4; i++)
#pragma unroll
            for (int j = 0; j < 4; j++) {
                acc[i][j] += a[i].x * b[j].x;
                acc[i][j] += a[i].y * b[j].y;
                acc[i][j] += a[i].z * b[j].z;
                acc[i][j] += a[i].w * b[j].w;
            }
    }
#pragma unroll
    for (int i = 0; i < 4; i++) {
        float4 v = make_float4(acc[i][0], acc[i][1], acc[i][2], acc[i][3]);
        *(float4*)(dst + (size_t)(ty * 4 + i) * cstride + c0 + tx * 4) = v;
    }
}

__global__ void __launch_bounds__(256, 2)
k_pool_all(const float* __restrict__ x, const float* __restrict__ prompt,
           const float* __restrict__ W, float* __restrict__ out) {
    __shared__ float s_pool[2 * 64 * 68];   // 34.8 KB, phase-unioned
    int tid = threadIdx.x, bid = blockIdx.x;
    int lane = tid & 31, wid = tid >> 5;

    // ---------------- phase 0: token-max stream (403 MB) ----------------
    {
        const float4* x4 = (const float4*)x;
        for (int tile = bid; tile < SPLITS * BATCH; tile += G) {
            int s = tile >> 6, b = tile & 63;
            if (tid < 192) {
                const float4* xp = x4 + ((size_t)b * TOK + (size_t)s * TOKS) * D4 + tid;
                float4 m0 = xp[0 * D4], m1 = xp[1 * D4], m2 = xp[2 * D4], m3 = xp[3 * D4];
                float4 m4 = xp[4 * D4], m5 = xp[5 * D4], m6 = xp[6 * D4], m7 = xp[7 * D4];
#pragma unroll
                for (int t = 8; t < TOKS; t += 8) {
                    m0 = fmax4(m0, xp[(t + 0) * D4]);
                    m1 = fmax4(m1, xp[(t + 1) * D4]);
                    m2 = fmax4(m2, xp[(t + 2) * D4]);
                    m3 = fmax4(m3, xp[(t + 3) * D4]);
                    m4 = fmax4(m4, xp[(t + 4) * D4]);
                    m5 = fmax4(m5, xp[(t + 5) * D4]);
                    m6 = fmax4(m6, xp[(t + 6) * D4]);
                    m7 = fmax4(m7, xp[(t + 7) * D4]);
                }
                float4 r = fmax4(fmax4(fmax4(m0, m1), fmax4(m2, m3)),
                                 fmax4(fmax4(m4, m5), fmax4(m6, m7)));
                ((float4*)g_part)[(size_t)tile * D4 + tid] = r;
            }
        }
    }
    grid_sync();

    // ---------------- phase 1: final max (64 CTAs) + prompt norms (rest) ----
    if (bid < BATCH) {
        int b = bid;
        if (tid < 192) {
            const float4* p4 = (const float4*)g_part;
            float4 m0 = p4[(0 * BATCH + b) * D4 + tid];
            float4 m1 = p4[(1 * BATCH + b) * D4 + tid];
            float4 m2 = p4[(2 * BATCH + b) * D4 + tid];
            float4 m3 = p4[(3 * BATCH + b) * D4 + tid];
#pragma unroll
            for (int s = 4; s < SPLITS; s += 4) {
                m0 = fmax4(m0, p4[((s + 0) * BATCH + b) * D4 + tid]);
                m1 = fmax4(m1, p4[((s + 1) * BATCH + b) * D4 + tid]);
                m2 = fmax4(m2, p4[((s + 2) * BATCH + b) * D4 + tid]);
                m3 = fmax4(m3, p4[((s + 3) * BATCH + b) * D4 + tid]);
            }
            ((float4*)g_xmean)[b * D4 + tid] = fmax4(fmax4(m0, m1), fmax4(m2, m3));
        }
    } else {
        int p = (bid - BATCH) * 8 + wid;   // 232 CTAs x 8 warps = 1856 >= 1024
        if (p < POOL) {
            const float* row = prompt + (size_t)p * DIM;
            float s = 0.f;
#pragma unroll
            for (int j = lane; j < DIM; j += 32) { float v = row[j]; s += v * v; }
#pragma unroll
            for (int o = 16; o > 0; o >>= 1) s += __shfl_xor_sync(0xffffffffu, s, o);
            if (lane == 0) g_invp[p] = rsqrtf(fmaxf(s, 1e-12f));
        }
    }
    grid_sync();

    // ---------------- phase 2: proj split-K GEMM (144 jobs) -----------------
    if (bid < NK * (DIM / 64)) {           // 144
        int ct = bid % (DIM / 64), kt = bid / (DIM / 64);
        gemm64(g_xmean, W, g_ppart + (size_t)kt * BATCH * DIM, DIM,
               kt * KC, ct * 64, s_pool);
    }
    grid_sync();

    // ---------------- phase 3: reduce proj partials + L2 norm (64 CTAs) -----
    if (bid < BATCH) {
        int b = bid;
        float v[3], ss = 0.f;
#pragma unroll
        for (int j = 0; j < 3; j++) {
            int col = tid + 256 * j;
            float s = 0.f;
#pragma unroll
            for (int sp = 0; sp < NK; sp++)
                s += g_ppart[(size_t)sp * BATCH * DIM + (size_t)b * DIM + col];
            v[j] = s; ss += s * s;
        }
        float* red = s_pool;
        red[tid] = ss; __syncthreads();
        for (int st = 128; st > 0; st >>= 1) {
            if (tid < st) red[tid] += red[tid + st];
            __syncthreads();
        }
        if (tid == 0) s_pool[260] = rsqrtf(fmaxf(red[0], 1e-12f));
        __syncthreads();
        float inv = s_pool[260];
#pragma unroll
        for (int j = 0; j < 3; j++)
            g_xnorm[b * DIM + tid + 256 * j] = v[j] * inv;
    }
    grid_sync();

    // ---------------- phase 4: sim split-K GEMM (192 jobs) ------------------
    if (bid < NK * (POOL / 64)) {          // 192
        int ct = bid % (POOL / 64), kt = bid / (POOL / 64);
        gemm64(g_xnorm, prompt, g_spart + (size_t)kt * BATCH * POOL, POOL,
               kt * KC, ct * 64, s_pool);
    }
    grid_sync();

    // ---------------- phase 5: reduce sim + scale + per-row top-8 (64 CTAs) -
    if (bid < BATCH) {
        int b = bid;
        float* sv = s_pool;                          // [1024]
        float* rv = s_pool + POOL;                   // [256]
        int*   ri = (int*)(s_pool + POOL + 256);     // [256]
#pragma unroll
        for (int j = 0; j < 4; j++) {
            int p = tid + 256 * j;
            float s = 0.f;
#pragma unroll
            for (int sp = 0; sp < NK; sp++)
                s += g_spart[(size_t)sp * BATCH * POOL + (size_t)b * POOL + p];
            s *= g_invp[p];
            sv[p] = s;
            g_sim[b * POOL + p] = s;
        }
        __syncthreads();
        for (int k = 0; k < TOPK; k++) {
            float bv = -FLT_MAX; int bi = 0;
#pragma unroll
            for (int j = 0; j < 4; j++) {
                int i = tid + 256 * j;
                float v = sv[i];
                if (v > bv) { bv = v; bi = i; }   // ascending i: lowest idx on tie
            }
            rv[tid] = bv; ri[tid] = bi; __syncthreads();
            for (int st = 128; st > 0; st >>= 1) {
                if (tid < st) {
                    float v2 = rv[tid + st]; int i2 = ri[tid + st];
                    if (v2 > rv[tid] || (v2 == rv[tid] && i2 < ri[tid])) { rv[tid] = v2; ri[tid] = i2; }
                }
                __syncthreads();
            }
            if (tid == 0) { g_rowidx[b * TOPK + k] = ri[0]; sv[ri[0]] = -FLT_MAX; }
            __syncthreads();
        }
    }
    grid_sync();

    // ---------------- phase 6: vote + reduce_sim (CTA 0) --------------------
    if (bid == 0) {
        int*   cnt     = (int*)s_pool;                 // [1024]
        int*   rvi     = (int*)(s_pool + 1024);        // [256]
        int*   ri      = (int*)(s_pool + 1280);        // [256]
        float* rf      = s_pool + 1536;                // [256]
        int*   major_s = (int*)(s_pool + 1792);        // [8]
        for (int j = tid; j < POOL; j += 256) cnt[j] = 0;
        __syncthreads();
        for (int j = tid; j < BATCH * TOPK; j += 256) atomicAdd(&cnt[g_rowidx[j]], 1);
        __syncthreads();
        for (int k = 0; k < TOPK; k++) {
            int bv = -1, bi = 0;
            for (int j = tid; j < POOL; j += 256) {
                int c = cnt[j];
                if (c > bv) { bv = c; bi = j; }
            }
            rvi[tid] = bv; ri[tid] = bi; __syncthreads();
            for (int st = 128; st > 0; st >>= 1) {
                if (tid < st) {
                    int v2 = rvi[tid + st], i2 = ri[tid + st];
                    if (v2 > rvi[tid] || (v2 == rvi[tid] && i2 < ri[tid])) { rvi[tid] = v2; ri[tid] = i2; }
                }
                __syncthreads();
            }
            if (tid == 0) { major_s[k] = ri[0]; g_major[k] = ri[0]; cnt[ri[0]] = -1; }
            __syncthreads();
        }
        float s = 0.f;
        for (int j = tid; j < BATCH * TOPK; j += 256) {
            int b = j >> 3, k = j & 7;
            s += g_sim[b * POOL + major_s[k]];
        }
        rf[tid] = s; __syncthreads();
        for (int st = 128; st > 0; st >>= 1) {
            if (tid < st) rf[tid] += rf[tid + st];
            __syncthreads();
        }
        if (tid == 0) out[0] = rf[0] / (float)BATCH;
    }
    grid_sync();

    // ---------------- phase 7: gather batched_prompt (all CTAs) -------------
    // NOTE: dst = out + 1 + ... is only 4-byte aligned -> scalar stores only.
    for (int row = bid; row < BATCH * TOPK; row += G) {
        int k = row & 7;
        int pid = g_major[k];
        const float* src = prompt + (size_t)pid * DIM;
        float* dst = out + 1 + (size_t)row * DIM;
        if (tid < 192) {
            float4 v = ((const float4*)src)[tid];   // src IS 16B-aligned
            dst[tid * 4 + 0] = v.x;
            dst[tid * 4 + 1] = v.y;
            dst[tid * 4 + 2] = v.z;
            dst[tid * 4 + 3] = v.w;
        }
    }
}

extern "C" void kernel_launch(void* const* d_in, const int* in_sizes, int n_in,
                              void* d_out, int out_size) {
    const float* x      = (const float*)d_in[0];   // [64, 2048, 768]
    const float* prompt = (const float*)d_in[1];   // [1024, 768]
    const float* W      = (const float*)d_in[2];   // [768, 768]
    float* out = (float*)d_out;                    // [1 + 64*8*768]
    k_pool_all<<<G, 256>>>(x, prompt, W, out);
}